// round 15
// baseline (speedup 1.0000x reference)
#include <cuda_runtime.h>
#include <cuda_fp16.h>
#include <cstdint>
#include <cstddef>

#define HIDDEN 2048
#define INTER  1408
#define TOKENS 4096
#define NEXP   8
#define MAX_MTILES 72
#define MAX_SLOTS  (MAX_MTILES * 128)   // 9216

// ---------------- device scratch ----------------
__device__ __align__(16) __half g_X[(size_t)MAX_SLOTS * HIDDEN];
__device__ __align__(16) __half g_Wg[(size_t)NEXP * HIDDEN * INTER]; // direct copy [e][h][i]
__device__ __align__(16) __half g_Wu[(size_t)NEXP * HIDDEN * INTER]; // direct copy [e][h][i]
__device__ __align__(16) __half g_Wd[(size_t)NEXP * INTER * HIDDEN]; // direct copy [e][i][h]
__device__ __align__(16) __half g_H[(size_t)MAX_SLOTS * INTER];
__device__ __align__(16) __half g_Oh[(size_t)MAX_SLOTS * HIDDEN];    // pre-weighted fp16

__device__ int   g_top_idx[TOKENS * 2];
__device__ float g_top_w[TOKENS * 2];
__device__ int   g_counts[NEXP];
__device__ int   g_tile_expert[MAX_MTILES];
__device__ int   g_tile_slot0[MAX_MTILES];
__device__ int   g_perm_token[MAX_SLOTS];
__device__ float g_perm_w[MAX_SLOTS];
__device__ int   g_token_slot[TOKENS * 2];

// ---------------- PTX helpers ----------------
__device__ __forceinline__ uint32_t smem_u32(const void* p) {
    uint32_t a;
    asm("{ .reg .u64 t; cvta.to.shared.u64 t, %1; cvt.u32.u64 %0, t; }" : "=r"(a) : "l"(p));
    return a;
}
#define CP_ASYNC16(sa, gp) asm volatile("cp.async.cg.shared.global [%0], [%1], 16;" :: "r"(sa), "l"(gp))
#define CP_COMMIT()        asm volatile("cp.async.commit_group;" ::: "memory")
#define CP_WAIT0()         asm volatile("cp.async.wait_group 0;" ::: "memory")
#define CP_WAIT1()         asm volatile("cp.async.wait_group 1;" ::: "memory")

__device__ __forceinline__ void ldm_x4(uint32_t* r, uint32_t addr) {
    asm volatile("ldmatrix.sync.aligned.m8n8.x4.shared.b16 {%0,%1,%2,%3}, [%4];"
                 : "=r"(r[0]), "=r"(r[1]), "=r"(r[2]), "=r"(r[3]) : "r"(addr));
}
__device__ __forceinline__ void ldm_x2_trans(uint32_t* r, uint32_t addr) {
    asm volatile("ldmatrix.sync.aligned.m8n8.x2.trans.shared.b16 {%0,%1}, [%2];"
                 : "=r"(r[0]), "=r"(r[1]) : "r"(addr));
}
__device__ __forceinline__ void mma_f16(float* c, const uint32_t* a, const uint32_t* b) {
    asm volatile("mma.sync.aligned.m16n8k16.row.col.f32.f16.f16.f32 "
                 "{%0,%1,%2,%3}, {%4,%5,%6,%7}, {%8,%9}, {%0,%1,%2,%3};"
                 : "+f"(c[0]), "+f"(c[1]), "+f"(c[2]), "+f"(c[3])
                 : "r"(a[0]), "r"(a[1]), "r"(a[2]), "r"(a[3]), "r"(b[0]), "r"(b[1]));
}
__device__ __forceinline__ uint32_t sw128(uint32_t off) { return off ^ ((off >> 3) & 0x70); }

// ---------------- aux kernels ----------------
__global__ void moe_init_kernel() {
    int i = blockIdx.x * blockDim.x + threadIdx.x;
    if (i < NEXP) g_counts[i] = 0;
    if (i < MAX_SLOTS) { g_perm_token[i] = -1; g_perm_w[i] = 0.f; }
}

// fused streaming fp32 -> fp16 convert of all three weight tensors (no transpose)
__global__ void moe_convert_kernel(const float* __restrict__ wg, const float* __restrict__ wu,
                                   const float* __restrict__ wd) {
    const float* src;
    __half* dst;
    if (blockIdx.z == 0)      { src = wg; dst = g_Wg; }
    else if (blockIdx.z == 1) { src = wu; dst = g_Wu; }
    else                      { src = wd; dst = g_Wd; }
    size_t i = (size_t)blockIdx.x * blockDim.x + threadIdx.x;   // float4 index
    float4 v = reinterpret_cast<const float4*>(src)[i];
    __half2 h0 = __halves2half2(__float2half_rn(v.x), __float2half_rn(v.y));
    __half2 h1 = __halves2half2(__float2half_rn(v.z), __float2half_rn(v.w));
    uint2 pk;
    pk.x = *reinterpret_cast<uint32_t*>(&h0);
    pk.y = *reinterpret_cast<uint32_t*>(&h1);
    reinterpret_cast<uint2*>(dst)[i] = pk;
}

// block-per-token router, float4-vectorized
__global__ void moe_router_kernel(const float* __restrict__ x, const float* __restrict__ rw) {
    int t = blockIdx.x;
    const float4* xp = reinterpret_cast<const float4*>(x + (size_t)t * HIDDEN);
    float acc[NEXP];
#pragma unroll
    for (int e = 0; e < NEXP; e++) acc[e] = 0.f;
    for (int i = threadIdx.x; i < HIDDEN / 4; i += 256) {
        float4 xv = xp[i];
#pragma unroll
        for (int e = 0; e < NEXP; e++) {
            float4 wv = reinterpret_cast<const float4*>(rw + (size_t)e * HIDDEN)[i];
            acc[e] += xv.x * wv.x + xv.y * wv.y + xv.z * wv.z + xv.w * wv.w;
        }
    }
#pragma unroll
    for (int o = 16; o > 0; o >>= 1)
#pragma unroll
        for (int e = 0; e < NEXP; e++) acc[e] += __shfl_down_sync(0xFFFFFFFFu, acc[e], o);
    __shared__ float red[8][NEXP];
    int wid = threadIdx.x >> 5, lid = threadIdx.x & 31;
    if (lid == 0)
#pragma unroll
        for (int e = 0; e < NEXP; e++) red[wid][e] = acc[e];
    __syncthreads();
    if (threadIdx.x == 0) {
        float l[NEXP];
#pragma unroll
        for (int e = 0; e < NEXP; e++) {
            float s = 0.f;
            for (int w = 0; w < 8; w++) s += red[w][e];
            l[e] = s;
        }
        int i0 = 0;
        for (int e = 1; e < NEXP; e++) if (l[e] > l[i0]) i0 = e;
        int i1 = (i0 == 0) ? 1 : 0;
        for (int e = 0; e < NEXP; e++) if (e != i0 && l[e] > l[i1]) i1 = e;
        float e1 = __expf(l[i1] - l[i0]);
        float inv = 1.f / (1.f + e1);
        g_top_idx[t * 2 + 0] = i0;  g_top_w[t * 2 + 0] = inv;
        g_top_idx[t * 2 + 1] = i1;  g_top_w[t * 2 + 1] = e1 * inv;
        atomicAdd(&g_counts[i0], 1);
        atomicAdd(&g_counts[i1], 1);
    }
}

// fused schedule + assign: single block, smem atomics
__global__ void moe_sched_assign_kernel() {
    __shared__ int s_base[NEXP];
    __shared__ int s_pos[NEXP];
    int tid = threadIdx.x;
    if (tid == 0) {
        int base = 0, mt = 0;
        for (int e = 0; e < NEXP; e++) {
            s_base[e] = base;
            int nt = (g_counts[e] + 127) >> 7;
            for (int i = 0; i < nt && mt < MAX_MTILES; i++) {
                g_tile_expert[mt] = e;
                g_tile_slot0[mt] = base + i * 128;
                mt++;
            }
            base += nt * 128;
        }
        for (; mt < MAX_MTILES; mt++) g_tile_expert[mt] = -1;
    }
    if (tid < NEXP) s_pos[tid] = 0;
    __syncthreads();
    for (int t = tid; t < TOKENS; t += 256) {
#pragma unroll
        for (int k = 0; k < 2; k++) {
            int e = g_top_idx[t * 2 + k];
            int p = atomicAdd(&s_pos[e], 1);
            int s = s_base[e] + p;
            g_perm_token[s] = t;
            g_perm_w[s] = g_top_w[t * 2 + k];
            g_token_slot[t * 2 + k] = s;
        }
    }
}

union U8 { ushort u[8]; uint4 q; };

__global__ void moe_gather_kernel(const float* __restrict__ x) {
    int s = blockIdx.x;
    int t = g_perm_token[s];
    int c = threadIdx.x * 8;
    float v[8];
    if (t >= 0) {
        const float4* xp = reinterpret_cast<const float4*>(x + (size_t)t * HIDDEN + c);
        float4 a = xp[0], b = xp[1];
        v[0]=a.x; v[1]=a.y; v[2]=a.z; v[3]=a.w; v[4]=b.x; v[5]=b.y; v[6]=b.z; v[7]=b.w;
    } else {
#pragma unroll
        for (int i = 0; i < 8; i++) v[i] = 0.f;
    }
    U8 hi;
#pragma unroll
    for (int i = 0; i < 8; i++) hi.u[i] = __half_as_ushort(__float2half_rn(v[i]));
    *reinterpret_cast<uint4*>(g_X + (size_t)s * HIDDEN + c) = hi.q;
}

// ---------------- smem loaders (256 threads) ----------------
// 128 rows x 64 halfs (128B rows) -> SW128 smem
__device__ __forceinline__ void load_plane128(const __half* __restrict__ src, int ldk,
                                              uint32_t plane, int tid) {
#pragma unroll
    for (int it = 0; it < 4; it++) {
        int idx = tid + it * 256;
        int row = idx >> 3, v = idx & 7;
        CP_ASYNC16(plane + sw128((uint32_t)(row * 128 + v * 16)), src + (size_t)row * ldk + v * 8);
    }
}
// 64 rows x 64 halfs
__device__ __forceinline__ void load_plane64(const __half* __restrict__ src, int ldk,
                                             uint32_t plane, int tid) {
#pragma unroll
    for (int it = 0; it < 2; it++) {
        int idx = tid + it * 256;
        int row = idx >> 3, v = idx & 7;
        CP_ASYNC16(plane + sw128((uint32_t)(row * 128 + v * 16)), src + (size_t)row * ldk + v * 8);
    }
}

__device__ __forceinline__ float silu_mul(float g, float u) {
    return g / (1.f + __expf(-g)) * u;
}

// ---------------- GEMM1: fused gate+up+SiLU; B row-major [K][N] via ldmatrix.trans ----------------
// stage: A 16K | Bg 8K | Bu 8K = 32KB; 3 stages = 96KB; 2 CTAs/SM
#define G1_STAGE 32768
#define G1_SMEM  (3 * G1_STAGE)
__global__ __launch_bounds__(256, 2) void moe_gemm1() {
    extern __shared__ char smem[];
    uint32_t sb = smem_u32(smem);
    int e = g_tile_expert[blockIdx.x];
    if (e < 0) return;
    int slot0 = g_tile_slot0[blockIdx.x];
    int n0 = blockIdx.y * 64;
    int tid = threadIdx.x, wid = tid >> 5, lane = tid & 31;
    int wm = wid & 1, wn = wid >> 1;   // warp tile: 64 rows x 16 cols (per matrix)

    const __half* A  = g_X + (size_t)slot0 * HIDDEN;
    const __half* Bg = g_Wg + (size_t)e * HIDDEN * INTER + n0;   // row k, col n
    const __half* Bu = g_Wu + (size_t)e * HIDDEN * INTER + n0;

    float ag[4][2][4], au[4][2][4];
#pragma unroll
    for (int i = 0; i < 4; i++)
#pragma unroll
        for (int j = 0; j < 2; j++)
#pragma unroll
            for (int c = 0; c < 4; c++) { ag[i][j][c] = 0.f; au[i][j][c] = 0.f; }

    const int NK = HIDDEN / 64;
#pragma unroll
    for (int s = 0; s < 2; s++) {
        uint32_t st = sb + (uint32_t)s * G1_STAGE;
        size_t k0 = (size_t)s * 64;
        load_plane128(A  + k0,         HIDDEN, st,          tid);
        load_plane64 (Bg + k0 * INTER, INTER,  st + 16384,  tid);
        load_plane64 (Bu + k0 * INTER, INTER,  st + 24576,  tid);
        CP_COMMIT();
    }

    uint32_t a_off[4], b_off[2];
#pragma unroll
    for (int mt = 0; mt < 4; mt++) {
        int row = wm * 64 + mt * 16 + (lane & 15);
        a_off[mt] = sw128((uint32_t)(row * 128 + (lane >> 4) * 16));
    }
#pragma unroll
    for (int nt = 0; nt < 2; nt++) {
        int cn = wn * 16 + nt * 8;                      // col within 64-wide plane
        b_off[nt] = sw128((uint32_t)((lane & 15) * 128 + cn * 2));   // row = k (trans load)
    }

    for (int kc = 0; kc < NK; kc++) {
        uint32_t cur = sb + (uint32_t)(kc % 3) * G1_STAGE;
        if (kc + 1 < NK) { CP_WAIT1(); } else { CP_WAIT0(); }
        __syncthreads();
        if (kc + 2 < NK) {
            uint32_t nxt = sb + (uint32_t)((kc + 2) % 3) * G1_STAGE;
            size_t k0 = (size_t)(kc + 2) * 64;
            load_plane128(A  + k0,         HIDDEN, nxt,          tid);
            load_plane64 (Bg + k0 * INTER, INTER,  nxt + 16384,  tid);
            load_plane64 (Bu + k0 * INTER, INTER,  nxt + 24576,  tid);
            CP_COMMIT();
        }
#pragma unroll
        for (int s = 0; s < 4; s++) {
            uint32_t ksA = (uint32_t)(s * 32);       // A: 16 halfs = 32B along row
            uint32_t ksB = (uint32_t)(s * 16 * 128); // B: 16 k-rows
            uint32_t af[4][4];
#pragma unroll
            for (int mt = 0; mt < 4; mt++)
                ldm_x4(af[mt], cur + (a_off[mt] ^ ksA));
#pragma unroll
            for (int nt = 0; nt < 2; nt++) {
                uint32_t bg[2], bu[2];
                ldm_x2_trans(bg, cur + 16384 + b_off[nt] + ksB);
                ldm_x2_trans(bu, cur + 24576 + b_off[nt] + ksB);
#pragma unroll
                for (int mt = 0; mt < 4; mt++) {
                    mma_f16(ag[mt][nt], af[mt], bg);
                    mma_f16(au[mt][nt], af[mt], bu);
                }
            }
        }
    }
    // SiLU epilogue -> H (fp16)
    int r_base = wm * 64 + (lane >> 2);
    int c_base = n0 + wn * 16 + (lane & 3) * 2;
#pragma unroll
    for (int mt = 0; mt < 4; mt++) {
#pragma unroll
        for (int nt = 0; nt < 2; nt++) {
            int c = c_base + nt * 8;
#pragma unroll
            for (int half_ = 0; half_ < 2; half_++) {
                int r = r_base + mt * 16 + half_ * 8;
                float h0 = silu_mul(ag[mt][nt][half_ * 2],     au[mt][nt][half_ * 2]);
                float h1 = silu_mul(ag[mt][nt][half_ * 2 + 1], au[mt][nt][half_ * 2 + 1]);
                size_t off = (size_t)(slot0 + r) * INTER + c;
                *reinterpret_cast<__half2*>(g_H + off) =
                    __halves2half2(__float2half_rn(h0), __float2half_rn(h1));
            }
        }
    }
}

// ---------------- GEMM2: down; B row-major [K][N] via ldmatrix.trans; pre-weighted fp16 out ----------------
// stage: A 16K | B 16K (two 64-col sub-planes) = 32KB; 3 stages = 96KB; 2 CTAs/SM
#define G2_STAGE 32768
#define G2_SMEM  (3 * G2_STAGE)
__global__ __launch_bounds__(256, 2) void moe_gemm2() {
    extern __shared__ char smem[];
    uint32_t sb = smem_u32(smem);
    int e = g_tile_expert[blockIdx.x];
    if (e < 0) return;
    int slot0 = g_tile_slot0[blockIdx.x];
    int n0 = blockIdx.y * 128;
    int tid = threadIdx.x, wid = tid >> 5, lane = tid & 31;
    int wm = wid & 1, wn = wid >> 1;   // warp tile 64 x 32

    const __half* A = g_H + (size_t)slot0 * INTER;
    const __half* B = g_Wd + (size_t)e * INTER * HIDDEN + n0;    // row k, col n

    float acc[4][4][4];
#pragma unroll
    for (int i = 0; i < 4; i++)
#pragma unroll
        for (int j = 0; j < 4; j++)
#pragma unroll
            for (int c = 0; c < 4; c++) acc[i][j][c] = 0.f;

    const int NK = INTER / 64;
#pragma unroll
    for (int s = 0; s < 2; s++) {
        uint32_t st = sb + (uint32_t)s * G2_STAGE;
        size_t k0 = (size_t)s * 64;
        load_plane128(A + k0,               INTER,  st,                 tid);
        load_plane64 (B + k0 * HIDDEN,      HIDDEN, st + 16384,         tid);
        load_plane64 (B + k0 * HIDDEN + 64, HIDDEN, st + 16384 + 8192,  tid);
        CP_COMMIT();
    }

    uint32_t a_off[4], b_off[4];
#pragma unroll
    for (int mt = 0; mt < 4; mt++) {
        int row = wm * 64 + mt * 16 + (lane & 15);
        a_off[mt] = sw128((uint32_t)(row * 128 + (lane >> 4) * 16));
    }
#pragma unroll
    for (int nt = 0; nt < 4; nt++) {
        int cg = wn * 32 + nt * 8;                 // global col within 128-wide tile
        int p = cg >> 6, cin = cg & 63;            // sub-plane + col within
        b_off[nt] = (uint32_t)(p * 8192) + sw128((uint32_t)((lane & 15) * 128 + cin * 2));
    }

    for (int kc = 0; kc < NK; kc++) {
        uint32_t cur = sb + (uint32_t)(kc % 3) * G2_STAGE;
        if (kc + 1 < NK) { CP_WAIT1(); } else { CP_WAIT0(); }
        __syncthreads();
        if (kc + 2 < NK) {
            uint32_t nxt = sb + (uint32_t)((kc + 2) % 3) * G2_STAGE;
            size_t k0 = (size_t)(kc + 2) * 64;
            load_plane128(A + k0,               INTER,  nxt,                 tid);
            load_plane64 (B + k0 * HIDDEN,      HIDDEN, nxt + 16384,         tid);
            load_plane64 (B + k0 * HIDDEN + 64, HIDDEN, nxt + 16384 + 8192,  tid);
            CP_COMMIT();
        }
#pragma unroll
        for (int s = 0; s < 4; s++) {
            uint32_t ksA = (uint32_t)(s * 32);
            uint32_t ksB = (uint32_t)(s * 16 * 128);
            uint32_t af[4][4];
#pragma unroll
            for (int mt = 0; mt < 4; mt++)
                ldm_x4(af[mt], cur + (a_off[mt] ^ ksA));
#pragma unroll
            for (int nt = 0; nt < 4; nt++) {
                uint32_t bf[2];
                ldm_x2_trans(bf, cur + 16384 + b_off[nt] + ksB);
#pragma unroll
                for (int mt = 0; mt < 4; mt++)
                    mma_f16(acc[mt][nt], af[mt], bf);
            }
        }
    }
    // pre-weighted fp16 epilogue
    int r_base = wm * 64 + (lane >> 2);
    int c_base = n0 + wn * 32 + (lane & 3) * 2;
#pragma unroll
    for (int mt = 0; mt < 4; mt++) {
#pragma unroll
        for (int half_ = 0; half_ < 2; half_++) {
            int r = r_base + mt * 16 + half_ * 8;
            float w = g_perm_w[slot0 + r];
            __half* orow = g_Oh + (size_t)(slot0 + r) * HIDDEN;
#pragma unroll
            for (int nt = 0; nt < 4; nt++) {
                int c = c_base + nt * 8;
                float v0 = w * acc[mt][nt][half_ * 2];
                float v1 = w * acc[mt][nt][half_ * 2 + 1];
                *reinterpret_cast<__half2*>(orow + c) =
                    __halves2half2(__float2half_rn(v0), __float2half_rn(v1));
            }
        }
    }
}

__global__ void moe_combine_kernel(float* __restrict__ out) {
    int t = blockIdx.x;
    int c = threadIdx.x * 8;
    int s0 = g_token_slot[t * 2], s1 = g_token_slot[t * 2 + 1];
    const __half2* a = reinterpret_cast<const __half2*>(g_Oh + (size_t)s0 * HIDDEN + c);
    const __half2* b = reinterpret_cast<const __half2*>(g_Oh + (size_t)s1 * HIDDEN + c);
    float* o = out + (size_t)t * HIDDEN + c;
#pragma unroll
    for (int j = 0; j < 4; j++) {
        float2 av = __half22float2(a[j]);
        float2 bv = __half22float2(b[j]);
        *reinterpret_cast<float2*>(o + j * 2) = make_float2(av.x + bv.x, av.y + bv.y);
    }
}

// ---------------- launch ----------------
extern "C" void kernel_launch(void* const* d_in, const int* in_sizes, int n_in,
                              void* d_out, int out_size) {
    const float* x  = (const float*)d_in[0];
    const float* rw = (const float*)d_in[1];
    const float* wg = (const float*)d_in[2];
    const float* wu = (const float*)d_in[3];
    const float* wd = (const float*)d_in[4];
    float* out = (float*)d_out;

    cudaFuncSetAttribute(moe_gemm1, cudaFuncAttributeMaxDynamicSharedMemorySize, G1_SMEM);
    cudaFuncSetAttribute(moe_gemm2, cudaFuncAttributeMaxDynamicSharedMemorySize, G2_SMEM);

    // elements per weight tensor = 8*2048*1408 = 23,068,672; /4 per thread /256 per block = 22528 blocks
    const int conv_blocks = (NEXP * HIDDEN * INTER / 4) / 256;

    moe_init_kernel<<<(MAX_SLOTS + 255) / 256, 256>>>();
    moe_convert_kernel<<<dim3(conv_blocks, 1, 3), 256>>>(wg, wu, wd);
    moe_router_kernel<<<TOKENS, 256>>>(x, rw);
    moe_sched_assign_kernel<<<1, 256>>>();
    moe_gather_kernel<<<MAX_SLOTS, 256>>>(x);
    moe_gemm1<<<dim3(MAX_MTILES, INTER / 64), 256, G1_SMEM>>>();
    moe_gemm2<<<dim3(MAX_MTILES, HIDDEN / 128), 256, G2_SMEM>>>();
    moe_combine_kernel<<<TOKENS, 256>>>(out);
}

// round 16
// speedup vs baseline: 1.4540x; 1.4540x over previous
#include <cuda_runtime.h>
#include <cuda_fp16.h>
#include <cstdint>
#include <cstddef>

#define HIDDEN 2048
#define INTER  1408
#define TOKENS 4096
#define NEXP   8
#define MAX_MTILES 72
#define MAX_SLOTS  (MAX_MTILES * 128)   // 9216

// ---------------- device scratch ----------------
__device__ __align__(16) __half g_X[(size_t)MAX_SLOTS * HIDDEN];
__device__ __align__(16) __half g_Wg[(size_t)NEXP * INTER * HIDDEN]; // [e][i][h]
__device__ __align__(16) __half g_Wu[(size_t)NEXP * INTER * HIDDEN];
__device__ __align__(16) __half g_Wd[(size_t)NEXP * HIDDEN * INTER]; // [e][h][i]
__device__ __align__(16) __half g_H[(size_t)MAX_SLOTS * INTER];
__device__ __align__(16) __half g_Oh[(size_t)MAX_SLOTS * HIDDEN];    // pre-weighted fp16

__device__ int   g_top_idx[TOKENS * 2];
__device__ float g_top_w[TOKENS * 2];
__device__ int   g_counts[NEXP];
__device__ int   g_pos[NEXP];
__device__ int   g_expert_base[NEXP];
__device__ int   g_tile_expert[MAX_MTILES];
__device__ int   g_tile_slot0[MAX_MTILES];
__device__ int   g_perm_token[MAX_SLOTS];
__device__ float g_perm_w[MAX_SLOTS];
__device__ int   g_token_slot[TOKENS * 2];

// ---------------- PTX helpers ----------------
__device__ __forceinline__ uint32_t smem_u32(const void* p) {
    uint32_t a;
    asm("{ .reg .u64 t; cvta.to.shared.u64 t, %1; cvt.u32.u64 %0, t; }" : "=r"(a) : "l"(p));
    return a;
}
#define CP_ASYNC16(sa, gp) asm volatile("cp.async.cg.shared.global [%0], [%1], 16;" :: "r"(sa), "l"(gp))
#define CP_COMMIT()        asm volatile("cp.async.commit_group;" ::: "memory")
#define CP_WAIT0()         asm volatile("cp.async.wait_group 0;" ::: "memory")
#define CP_WAIT1()         asm volatile("cp.async.wait_group 1;" ::: "memory")

__device__ __forceinline__ void ldm_x4(uint32_t* r, uint32_t addr) {
    asm volatile("ldmatrix.sync.aligned.m8n8.x4.shared.b16 {%0,%1,%2,%3}, [%4];"
                 : "=r"(r[0]), "=r"(r[1]), "=r"(r[2]), "=r"(r[3]) : "r"(addr));
}
__device__ __forceinline__ void ldm_x2(uint32_t* r, uint32_t addr) {
    asm volatile("ldmatrix.sync.aligned.m8n8.x2.shared.b16 {%0,%1}, [%2];"
                 : "=r"(r[0]), "=r"(r[1]) : "r"(addr));
}
__device__ __forceinline__ void mma_f16(float* c, const uint32_t* a, const uint32_t* b) {
    asm volatile("mma.sync.aligned.m16n8k16.row.col.f32.f16.f16.f32 "
                 "{%0,%1,%2,%3}, {%4,%5,%6,%7}, {%8,%9}, {%0,%1,%2,%3};"
                 : "+f"(c[0]), "+f"(c[1]), "+f"(c[2]), "+f"(c[3])
                 : "r"(a[0]), "r"(a[1]), "r"(a[2]), "r"(a[3]), "r"(b[0]), "r"(b[1]));
}
__device__ __forceinline__ uint32_t sw128(uint32_t off) { return off ^ ((off >> 3) & 0x70); }

// ---------------- aux kernels ----------------
__global__ void moe_init_kernel() {
    int i = blockIdx.x * blockDim.x + threadIdx.x;
    if (i < NEXP) { g_counts[i] = 0; g_pos[i] = 0; }
    if (i < MAX_SLOTS) { g_perm_token[i] = -1; g_perm_w[i] = 0.f; }
}

// block-per-token router (measured 30us)
__global__ void moe_router_kernel(const float* __restrict__ x, const float* __restrict__ rw) {
    int t = blockIdx.x;
    float acc[NEXP];
#pragma unroll
    for (int e = 0; e < NEXP; e++) acc[e] = 0.f;
    for (int c = threadIdx.x; c < HIDDEN; c += 256) {
        float xv = x[(size_t)t * HIDDEN + c];
#pragma unroll
        for (int e = 0; e < NEXP; e++) acc[e] += xv * rw[e * HIDDEN + c];
    }
#pragma unroll
    for (int o = 16; o > 0; o >>= 1)
#pragma unroll
        for (int e = 0; e < NEXP; e++) acc[e] += __shfl_down_sync(0xFFFFFFFFu, acc[e], o);
    __shared__ float red[8][NEXP];
    int wid = threadIdx.x >> 5, lid = threadIdx.x & 31;
    if (lid == 0)
#pragma unroll
        for (int e = 0; e < NEXP; e++) red[wid][e] = acc[e];
    __syncthreads();
    if (threadIdx.x == 0) {
        float l[NEXP];
#pragma unroll
        for (int e = 0; e < NEXP; e++) {
            float s = 0.f;
            for (int w = 0; w < 8; w++) s += red[w][e];
            l[e] = s;
        }
        int i0 = 0;
        for (int e = 1; e < NEXP; e++) if (l[e] > l[i0]) i0 = e;
        int i1 = (i0 == 0) ? 1 : 0;
        for (int e = 0; e < NEXP; e++) if (e != i0 && l[e] > l[i1]) i1 = e;
        float e1 = __expf(l[i1] - l[i0]);
        float inv = 1.f / (1.f + e1);
        g_top_idx[t * 2 + 0] = i0;  g_top_w[t * 2 + 0] = inv;
        g_top_idx[t * 2 + 1] = i1;  g_top_w[t * 2 + 1] = e1 * inv;
        atomicAdd(&g_counts[i0], 1);
        atomicAdd(&g_counts[i1], 1);
    }
}

__global__ void moe_schedule_kernel() {
    int base = 0, mt = 0;
    for (int e = 0; e < NEXP; e++) {
        g_expert_base[e] = base;
        int nt = (g_counts[e] + 127) >> 7;
        for (int i = 0; i < nt && mt < MAX_MTILES; i++) {
            g_tile_expert[mt] = e;
            g_tile_slot0[mt] = base + i * 128;
            mt++;
        }
        base += nt * 128;
    }
    for (; mt < MAX_MTILES; mt++) g_tile_expert[mt] = -1;
}

__global__ void moe_assign_kernel() {
    int t = blockIdx.x * blockDim.x + threadIdx.x;
    if (t >= TOKENS) return;
#pragma unroll
    for (int k = 0; k < 2; k++) {
        int e = g_top_idx[t * 2 + k];
        int p = atomicAdd(&g_pos[e], 1);
        int s = g_expert_base[e] + p;
        g_perm_token[s] = t;
        g_perm_w[s] = g_top_w[t * 2 + k];
        g_token_slot[t * 2 + k] = s;
    }
}

union U8 { ushort u[8]; uint4 q; };

__global__ void moe_gather_kernel(const float* __restrict__ x) {
    int s = blockIdx.x;
    int t = g_perm_token[s];
    int c = threadIdx.x * 8;
    float v[8];
    if (t >= 0) {
        const float4* xp = reinterpret_cast<const float4*>(x + (size_t)t * HIDDEN + c);
        float4 a = xp[0], b = xp[1];
        v[0]=a.x; v[1]=a.y; v[2]=a.z; v[3]=a.w; v[4]=b.x; v[5]=b.y; v[6]=b.z; v[7]=b.w;
    } else {
#pragma unroll
        for (int i = 0; i < 8; i++) v[i] = 0.f;
    }
    U8 hi;
#pragma unroll
    for (int i = 0; i < 8; i++) hi.u[i] = __half_as_ushort(__float2half_rn(v[i]));
    *reinterpret_cast<uint4*>(g_X + (size_t)s * HIDDEN + c) = hi.q;
}

// ---------------- transposes: float4 loads, packed 4-half stores. 256 flat threads ----------------
__global__ void moe_transpose_gu_kernel(const float* __restrict__ wg, const float* __restrict__ wu) {
    __shared__ float tile[32][33];
    int z = blockIdx.z;
    int e = z & 7, sel = z >> 3;
    const int R = HIDDEN, C = INTER;
    const float* s = (sel ? wu : wg) + (size_t)e * R * C;
    __half* dh = (sel ? g_Wu : g_Wg) + (size_t)e * R * C;
    int c0 = blockIdx.x * 32, r0 = blockIdx.y * 32;
    int tid = threadIdx.x;
    int row = tid >> 3, c4 = (tid & 7) << 2;
    float4 v = *reinterpret_cast<const float4*>(s + (size_t)(r0 + row) * C + c0 + c4);
    tile[row][c4] = v.x; tile[row][c4 + 1] = v.y; tile[row][c4 + 2] = v.z; tile[row][c4 + 3] = v.w;
    __syncthreads();
    int oc = tid >> 3, r4 = (tid & 7) << 2;
    __half h[4];
#pragma unroll
    for (int j = 0; j < 4; j++) h[j] = __float2half_rn(tile[r4 + j][oc]);
    *reinterpret_cast<uint2*>(dh + (size_t)(c0 + oc) * R + (r0 + r4)) = *reinterpret_cast<uint2*>(h);
}

__global__ void moe_transpose_d_kernel(const float* __restrict__ wd) {
    __shared__ float tile[32][33];
    int e = blockIdx.z;
    const int R = INTER, C = HIDDEN;
    const float* s = wd + (size_t)e * R * C;
    __half* dh = g_Wd + (size_t)e * R * C;
    int c0 = blockIdx.x * 32, r0 = blockIdx.y * 32;
    int tid = threadIdx.x;
    int row = tid >> 3, c4 = (tid & 7) << 2;
    float4 v = *reinterpret_cast<const float4*>(s + (size_t)(r0 + row) * C + c0 + c4);
    tile[row][c4] = v.x; tile[row][c4 + 1] = v.y; tile[row][c4 + 2] = v.z; tile[row][c4 + 3] = v.w;
    __syncthreads();
    int oc = tid >> 3, r4 = (tid & 7) << 2;
    __half h[4];
#pragma unroll
    for (int j = 0; j < 4; j++) h[j] = __float2half_rn(tile[r4 + j][oc]);
    *reinterpret_cast<uint2*>(dh + (size_t)(c0 + oc) * R + (r0 + r4)) = *reinterpret_cast<uint2*>(h);
}

// ---------------- smem loaders (256 threads) ----------------
__device__ __forceinline__ void load_plane128(const __half* __restrict__ src, int ldk,
                                              uint32_t plane, int tid) {
#pragma unroll
    for (int it = 0; it < 4; it++) {
        int idx = tid + it * 256;
        int row = idx >> 3, v = idx & 7;
        CP_ASYNC16(plane + sw128((uint32_t)(row * 128 + v * 16)), src + (size_t)row * ldk + v * 8);
    }
}
__device__ __forceinline__ void load_plane64(const __half* __restrict__ src, int ldk,
                                             uint32_t plane, int tid) {
#pragma unroll
    for (int it = 0; it < 2; it++) {
        int idx = tid + it * 256;
        int row = idx >> 3, v = idx & 7;
        CP_ASYNC16(plane + sw128((uint32_t)(row * 128 + v * 16)), src + (size_t)row * ldk + v * 8);
    }
}

__device__ __forceinline__ float silu_mul(float g, float u) {
    return g / (1.f + __expf(-g)) * u;
}

// ---------------- GEMM1: fused gate+up+SiLU, single-pass fp16 ----------------
// stage: A 16K | Bg 8K | Bu 8K = 32KB; 3 stages = 96KB; 2 CTAs/SM
#define G1_STAGE 32768
#define G1_SMEM  (3 * G1_STAGE)
__global__ __launch_bounds__(256, 2) void moe_gemm1() {
    extern __shared__ char smem[];
    uint32_t sb = smem_u32(smem);
    int e = g_tile_expert[blockIdx.x];
    if (e < 0) return;
    int slot0 = g_tile_slot0[blockIdx.x];
    int n0 = blockIdx.y * 64;
    int tid = threadIdx.x, wid = tid >> 5, lane = tid & 31;
    int wm = wid & 1, wn = wid >> 1;   // warp tile: 64 rows x 16 cols (per matrix)

    const __half* A  = g_X + (size_t)slot0 * HIDDEN;
    const __half* Bg = g_Wg + ((size_t)e * INTER + n0) * HIDDEN;
    const __half* Bu = g_Wu + ((size_t)e * INTER + n0) * HIDDEN;

    float ag[4][2][4], au[4][2][4];
#pragma unroll
    for (int i = 0; i < 4; i++)
#pragma unroll
        for (int j = 0; j < 2; j++)
#pragma unroll
            for (int c = 0; c < 4; c++) { ag[i][j][c] = 0.f; au[i][j][c] = 0.f; }

    const int NK = HIDDEN / 64;
#pragma unroll
    for (int s = 0; s < 2; s++) {
        uint32_t st = sb + (uint32_t)s * G1_STAGE;
        int k0 = s * 64;
        load_plane128(A  + k0, HIDDEN, st,          tid);
        load_plane64 (Bg + k0, HIDDEN, st + 16384,  tid);
        load_plane64 (Bu + k0, HIDDEN, st + 24576,  tid);
        CP_COMMIT();
    }

    uint32_t a_off[4], b_off[2];
#pragma unroll
    for (int mt = 0; mt < 4; mt++) {
        int row = wm * 64 + mt * 16 + (lane & 15);
        a_off[mt] = sw128((uint32_t)(row * 128 + (lane >> 4) * 16));
    }
#pragma unroll
    for (int nt = 0; nt < 2; nt++) {
        int row = wn * 16 + nt * 8 + (lane & 7);
        b_off[nt] = sw128((uint32_t)(row * 128 + ((lane >> 3) & 1) * 16));
    }

    for (int kc = 0; kc < NK; kc++) {
        uint32_t cur = sb + (uint32_t)(kc % 3) * G1_STAGE;
        if (kc + 1 < NK) { CP_WAIT1(); } else { CP_WAIT0(); }
        __syncthreads();
        if (kc + 2 < NK) {
            uint32_t nxt = sb + (uint32_t)((kc + 2) % 3) * G1_STAGE;
            int k0 = (kc + 2) * 64;
            load_plane128(A  + k0, HIDDEN, nxt,          tid);
            load_plane64 (Bg + k0, HIDDEN, nxt + 16384,  tid);
            load_plane64 (Bu + k0, HIDDEN, nxt + 24576,  tid);
            CP_COMMIT();
        }
#pragma unroll
        for (int s = 0; s < 4; s++) {
            uint32_t ks = (uint32_t)(s * 32);
            uint32_t af[4][4];
#pragma unroll
            for (int mt = 0; mt < 4; mt++)
                ldm_x4(af[mt], cur + (a_off[mt] ^ ks));
#pragma unroll
            for (int nt = 0; nt < 2; nt++) {
                uint32_t bg[2], bu[2];
                ldm_x2(bg, cur + 16384 + (b_off[nt] ^ ks));
                ldm_x2(bu, cur + 24576 + (b_off[nt] ^ ks));
#pragma unroll
                for (int mt = 0; mt < 4; mt++) {
                    mma_f16(ag[mt][nt], af[mt], bg);
                    mma_f16(au[mt][nt], af[mt], bu);
                }
            }
        }
    }
    // SiLU epilogue -> H (fp16)
    int r_base = wm * 64 + (lane >> 2);
    int c_base = n0 + wn * 16 + (lane & 3) * 2;
#pragma unroll
    for (int mt = 0; mt < 4; mt++) {
#pragma unroll
        for (int nt = 0; nt < 2; nt++) {
            int c = c_base + nt * 8;
#pragma unroll
            for (int half_ = 0; half_ < 2; half_++) {
                int r = r_base + mt * 16 + half_ * 8;
                float h0 = silu_mul(ag[mt][nt][half_ * 2],     au[mt][nt][half_ * 2]);
                float h1 = silu_mul(ag[mt][nt][half_ * 2 + 1], au[mt][nt][half_ * 2 + 1]);
                size_t off = (size_t)(slot0 + r) * INTER + c;
                *reinterpret_cast<__half2*>(g_H + off) =
                    __halves2half2(__float2half_rn(h0), __float2half_rn(h1));
            }
        }
    }
}

// ---------------- GEMM2: down, single-pass fp16, pre-weighted fp16 out ----------------
// stage: A 16K | B 16K = 32KB; 3 stages = 96KB; 2 CTAs/SM
#define G2_STAGE 32768
#define G2_SMEM  (3 * G2_STAGE)
__global__ __launch_bounds__(256, 2) void moe_gemm2() {
    extern __shared__ char smem[];
    uint32_t sb = smem_u32(smem);
    int e = g_tile_expert[blockIdx.x];
    if (e < 0) return;
    int slot0 = g_tile_slot0[blockIdx.x];
    int n0 = blockIdx.y * 128;
    int tid = threadIdx.x, wid = tid >> 5, lane = tid & 31;
    int wm = wid & 1, wn = wid >> 1;   // warp tile 64 x 32

    const __half* A = g_H + (size_t)slot0 * INTER;
    const __half* B = g_Wd + ((size_t)e * HIDDEN + n0) * INTER;

    float acc[4][4][4];
#pragma unroll
    for (int i = 0; i < 4; i++)
#pragma unroll
        for (int j = 0; j < 4; j++)
#pragma unroll
            for (int c = 0; c < 4; c++) acc[i][j][c] = 0.f;

    const int NK = INTER / 64;
#pragma unroll
    for (int s = 0; s < 2; s++) {
        uint32_t st = sb + (uint32_t)s * G2_STAGE;
        int k0 = s * 64;
        load_plane128(A + k0, INTER, st,          tid);
        load_plane128(B + k0, INTER, st + 16384,  tid);
        CP_COMMIT();
    }

    uint32_t a_off[4], b_off[4];
#pragma unroll
    for (int mt = 0; mt < 4; mt++) {
        int row = wm * 64 + mt * 16 + (lane & 15);
        a_off[mt] = sw128((uint32_t)(row * 128 + (lane >> 4) * 16));
    }
#pragma unroll
    for (int nt = 0; nt < 4; nt++) {
        int row = wn * 32 + nt * 8 + (lane & 7);
        b_off[nt] = sw128((uint32_t)(row * 128 + ((lane >> 3) & 1) * 16));
    }

    for (int kc = 0; kc < NK; kc++) {
        uint32_t cur = sb + (uint32_t)(kc % 3) * G2_STAGE;
        if (kc + 1 < NK) { CP_WAIT1(); } else { CP_WAIT0(); }
        __syncthreads();
        if (kc + 2 < NK) {
            uint32_t nxt = sb + (uint32_t)((kc + 2) % 3) * G2_STAGE;
            int k0 = (kc + 2) * 64;
            load_plane128(A + k0, INTER, nxt,          tid);
            load_plane128(B + k0, INTER, nxt + 16384,  tid);
            CP_COMMIT();
        }
#pragma unroll
        for (int s = 0; s < 4; s++) {
            uint32_t ks = (uint32_t)(s * 32);
            uint32_t af[4][4];
#pragma unroll
            for (int mt = 0; mt < 4; mt++)
                ldm_x4(af[mt], cur + (a_off[mt] ^ ks));
#pragma unroll
            for (int nt = 0; nt < 4; nt++) {
                uint32_t bf[2];
                ldm_x2(bf, cur + 16384 + (b_off[nt] ^ ks));
#pragma unroll
                for (int mt = 0; mt < 4; mt++)
                    mma_f16(acc[mt][nt], af[mt], bf);
            }
        }
    }
    // pre-weighted fp16 epilogue
    int r_base = wm * 64 + (lane >> 2);
    int c_base = n0 + wn * 32 + (lane & 3) * 2;
#pragma unroll
    for (int mt = 0; mt < 4; mt++) {
#pragma unroll
        for (int half_ = 0; half_ < 2; half_++) {
            int r = r_base + mt * 16 + half_ * 8;
            float w = g_perm_w[slot0 + r];
            __half* orow = g_Oh + (size_t)(slot0 + r) * HIDDEN;
#pragma unroll
            for (int nt = 0; nt < 4; nt++) {
                int c = c_base + nt * 8;
                float v0 = w * acc[mt][nt][half_ * 2];
                float v1 = w * acc[mt][nt][half_ * 2 + 1];
                *reinterpret_cast<__half2*>(orow + c) =
                    __halves2half2(__float2half_rn(v0), __float2half_rn(v1));
            }
        }
    }
}

__global__ void moe_combine_kernel(float* __restrict__ out) {
    int t = blockIdx.x;
    int c = threadIdx.x * 8;
    int s0 = g_token_slot[t * 2], s1 = g_token_slot[t * 2 + 1];
    const __half2* a = reinterpret_cast<const __half2*>(g_Oh + (size_t)s0 * HIDDEN + c);
    const __half2* b = reinterpret_cast<const __half2*>(g_Oh + (size_t)s1 * HIDDEN + c);
    float* o = out + (size_t)t * HIDDEN + c;
    float r[8];
#pragma unroll
    for (int j = 0; j < 4; j++) {
        float2 av = __half22float2(a[j]);
        float2 bv = __half22float2(b[j]);
        r[2 * j]     = av.x + bv.x;
        r[2 * j + 1] = av.y + bv.y;
    }
    *reinterpret_cast<float4*>(o)     = make_float4(r[0], r[1], r[2], r[3]);
    *reinterpret_cast<float4*>(o + 4) = make_float4(r[4], r[5], r[6], r[7]);
}

// ---------------- launch ----------------
extern "C" void kernel_launch(void* const* d_in, const int* in_sizes, int n_in,
                              void* d_out, int out_size) {
    const float* x  = (const float*)d_in[0];
    const float* rw = (const float*)d_in[1];
    const float* wg = (const float*)d_in[2];
    const float* wu = (const float*)d_in[3];
    const float* wd = (const float*)d_in[4];
    float* out = (float*)d_out;

    cudaFuncSetAttribute(moe_gemm1, cudaFuncAttributeMaxDynamicSharedMemorySize, G1_SMEM);
    cudaFuncSetAttribute(moe_gemm2, cudaFuncAttributeMaxDynamicSharedMemorySize, G2_SMEM);

    moe_init_kernel<<<(MAX_SLOTS + 255) / 256, 256>>>();
    moe_transpose_gu_kernel<<<dim3(INTER / 32, HIDDEN / 32, NEXP * 2), 256>>>(wg, wu);
    moe_transpose_d_kernel<<<dim3(HIDDEN / 32, INTER / 32, NEXP), 256>>>(wd);
    moe_router_kernel<<<TOKENS, 256>>>(x, rw);
    moe_schedule_kernel<<<1, 1>>>();
    moe_assign_kernel<<<(TOKENS + 255) / 256, 256>>>();
    moe_gather_kernel<<<MAX_SLOTS, 256>>>(x);
    moe_gemm1<<<dim3(MAX_MTILES, INTER / 64), 256, G1_SMEM>>>();
    moe_gemm2<<<dim3(MAX_MTILES, HIDDEN / 128), 256, G2_SMEM>>>();
    moe_combine_kernel<<<TOKENS, 256>>>(out);
}